// round 8
// baseline (speedup 1.0000x reference)
#include <cuda_runtime.h>
#include <cstdint>
#include <cstddef>

#define B 128
#define S 512
#define H 1024
#define NL 4
#define NCOL 3072      // only i,g,o gate blocks (f dead: c0=0; W_hh dead: h0=0)
#define KSPL 6         // K splits -> 24 x 6 = 144 CTAs = one wave
#define NT 24          // N tiles of 128
#define BN 128
#define KC 32          // k-floats per chunk (128 B rows)
#define PAD 36         // row pitch in floats (144 B, conflict-free, 16B-aligned)
#define STAGES 4
#define TXB 32768      // bytes per stage (256 rows x 128 B)

#define OUT_SH (S*B*H)            // 67108864
#define OUT_SC (S*B*H + NL*B*H)   // 67633152

// dynamic smem: [0,32) 4 mbarriers, tiles at 1024
// stage s: X rows at 1024 + s*36864 + row*144, W rows at +18432
#define SM_TILE0  1024
#define SM_STAGE  36864
#define SM_TOTAL  (1024 + STAGES*SM_STAGE)     // 148480 B
// float-index view for compute
#define XOFF(s) (SM_TILE0/4 + (s)*(SM_STAGE/4))
#define WOFF(s) (XOFF(s) + 128*PAD)

// ---------------- scratch (device globals; no allocation allowed) ----------
__device__ __align__(16) float g_xt[2][B*H];
__device__ __align__(16) float g_part[KSPL][NCOL*B];   // [n][b]-major partials
__device__ int g_len[B];
__device__ int g_rank[B];
__device__ int g_sorted[B];
__device__ int g_tok0[B];
__device__ int g_bslast;

// ---------------- PTX helpers ----------------------------------------------
__device__ __forceinline__ uint32_t smem_u32(const void* p) {
    uint32_t a;
    asm("{ .reg .u64 t; cvta.to.shared.u64 t, %1; cvt.u32.u64 %0, t; }" : "=r"(a) : "l"(p));
    return a;
}
__device__ __forceinline__ uint32_t f2tf32(float x) {
    uint32_t u;
    asm("cvt.rna.tf32.f32 %0, %1;" : "=r"(u) : "f"(x));
    return u;
}
__device__ __forceinline__ uint32_t bits2tf32(uint32_t r) {
    uint32_t u;
    asm("cvt.rna.tf32.f32 %0, %1;" : "=r"(u) : "f"(__uint_as_float(r)));
    return u;
}
#define MBAR_INIT(a, n) \
    asm volatile("mbarrier.init.shared.b64 [%0], %1;" :: "r"(a), "r"(n) : "memory")
#define MBAR_EXPECT_TX(a, n) \
    asm volatile("mbarrier.arrive.expect_tx.shared.b64 _, [%0], %1;" :: "r"(a), "r"(n) : "memory")
__device__ __forceinline__ void mbar_wait(uint32_t a, uint32_t par) {
    uint32_t done;
    asm volatile("{.reg .pred p; mbarrier.try_wait.parity.acquire.cta.shared::cta.b64 p, [%1], %2; selp.b32 %0,1,0,p;}"
                 : "=r"(done) : "r"(a), "r"(par) : "memory");
    while (!done) {
        asm volatile("{.reg .pred p; mbarrier.try_wait.parity.acquire.cta.shared::cta.b64 p, [%1], %2, 0x989680; selp.b32 %0,1,0,p;}"
                     : "=r"(done) : "r"(a), "r"(par) : "memory");
    }
}
__device__ __forceinline__ void bulk128(uint32_t dst, const void* src, uint32_t mbar) {
    asm volatile(
        "cp.async.bulk.shared::cluster.global.mbarrier::complete_tx::bytes [%0], [%1], 128, [%2];"
        :: "r"(dst), "l"(src), "r"(mbar) : "memory");
}
__device__ __forceinline__ void ldsm_x4(uint32_t* r, uint32_t addr) {
    asm volatile("ldmatrix.sync.aligned.m8n8.x4.shared.b16 {%0,%1,%2,%3}, [%4];"
                 : "=r"(r[0]), "=r"(r[1]), "=r"(r[2]), "=r"(r[3]) : "r"(addr));
}
__device__ __forceinline__ void mma_tf32(float* d, const uint32_t* a,
                                         uint32_t b0, uint32_t b1) {
    asm volatile(
        "mma.sync.aligned.m16n8k8.row.col.f32.tf32.tf32.f32 "
        "{%0,%1,%2,%3}, {%4,%5,%6,%7}, {%8,%9}, {%0,%1,%2,%3};"
        : "+f"(d[0]), "+f"(d[1]), "+f"(d[2]), "+f"(d[3])
        : "r"(a[0]), "r"(a[1]), "r"(a[2]), "r"(a[3]), "r"(b0), "r"(b1));
}

// ---------------- 1) lengths ----------------------------------------------
__global__ void len_kernel(const int* __restrict__ x) {
    int b = blockIdx.x, lane = threadIdx.x;
    int cnt = 0;
    #pragma unroll
    for (int s = lane; s < S; s += 32) cnt += (x[b*S + s] > 0);
    #pragma unroll
    for (int o = 16; o; o >>= 1) cnt += __shfl_down_sync(0xffffffffu, cnt, o);
    if (lane == 0) g_len[b] = cnt;
}

// ---------------- 2) stable descending argsort of 128 lengths -------------
__global__ void sort_kernel(const int* __restrict__ x) {
    __shared__ int slen[B];
    __shared__ int ssort[B];
    int b = threadIdx.x;
    slen[b] = g_len[b];
    __syncthreads();
    int lb = slen[b];
    int rank = 0, bs = 0;
    #pragma unroll 8
    for (int i = 0; i < B; i++) {
        int li = slen[i];
        rank += (li > lb) || (li == lb && i < b);
        bs += (li >= S);
    }
    g_rank[b] = rank;
    ssort[rank] = b;
    if (b == 0) g_bslast = bs;
    __syncthreads();
    int src = ssort[b];
    g_sorted[b] = src;
    g_tok0[b] = x[src * S];
}

// ---------------- 3) embedding gather (sorted order) ----------------------
__global__ void embed_kernel(const float* __restrict__ emb) {
    int i = blockIdx.x;
    int t = threadIdx.x;       // 256 threads, 1 float4 each (H = 1024)
    int tok = g_tok0[i];
    *(float4*)&g_xt[0][i*H + t*4] = *(const float4*)&emb[tok*H + t*4];
}

// ---------------- 4) tf32 mma.sync GEMM, cp.async.bulk pipeline -----------
// part[ks][n][b] = sum_{k in split} xt[b][k] * W[j(n)][k]
// mma-"A" = W (row-major n x k via ldmatrix b16 trick), mma-"B" = xt ([b][k])
__global__ __launch_bounds__(256, 1)
void gemm_mma(int sel, const float* __restrict__ W) {
    extern __shared__ __align__(16) float sm[];
    const uint32_t sb = smem_u32(sm);
    const int tid  = threadIdx.x;
    const int lane = tid & 31;
    const int warp = tid >> 5;            // 0..7
    const int wn = warp & 1;              // n half: 64 rows
    const int wb = warp >> 1;             // b quarter: 32 cols
    const int nt_ = blockIdx.x;           // 0..23
    const int ksp = blockIdx.y;           // 0..5
    const int n0 = nt_ * BN;
    const int j0 = (n0 < H) ? n0 : n0 + H;        // skip dead f-gate rows
    const int cnt = (ksp < 2) ? 6 : 5;            // chunks ({6,6,5,5,5,5} of 32)
    const int c0  = (ksp < 2) ? ksp*6 : 12 + (ksp-2)*5;
    const float* __restrict__ xt = g_xt[sel];

    // this thread's bulk-copy source row (one 128B row per stage)
    const int brow = tid & 127;
    const float* bsrc = (tid < 128) ? (xt + (size_t)brow*H)
                                    : (W + (size_t)(j0 + brow)*H);
    const uint32_t bdst0 = sb + SM_TILE0 + ((tid < 128) ? 0 : 18432) + brow*144;

    // ldmatrix lane address pieces (W operand)
    const int row_in = (lane & 7) + ((lane >> 3) & 1) * 8;
    const int kadd   = (lane >> 4) * 4;
    const int n0w    = wn * 64;
    const int b0w    = wb * 32;

    float acc[4][4][4];
    #pragma unroll
    for (int nt = 0; nt < 4; nt++)
        #pragma unroll
        for (int bt = 0; bt < 4; bt++)
            #pragma unroll
            for (int q = 0; q < 4; q++) acc[nt][bt][q] = 0.f;

    if (tid == 0) {
        #pragma unroll
        for (int s = 0; s < STAGES; s++) MBAR_INIT(sb + s*8, 1);
    }
    __syncthreads();

    // prologue: fire 3 stages (cnt >= 5 always)
    #pragma unroll
    for (int p = 0; p < 3; p++) {
        if (tid == 0) MBAR_EXPECT_TX(sb + p*8, TXB);
        bulk128(bdst0 + p*SM_STAGE, bsrc + (size_t)(c0 + p)*KC, sb + p*8);
    }

    for (int t = 0; t < cnt; t++) {
        const int buf = t & (STAGES - 1);
        mbar_wait(sb + buf*8, (t >> 2) & 1);

        const uint32_t wbase = sb + (WOFF(buf) + (n0w + row_in)*PAD + kadd) * 4;
        const int      xbase = XOFF(buf) + (b0w + (lane >> 2))*PAD + (lane & 3);
        #pragma unroll
        for (int kk = 0; kk < 4; kk++) {          // 4 k-steps of 8
            uint32_t a[4][4];
            #pragma unroll
            for (int nt = 0; nt < 4; nt++) {
                ldsm_x4(a[nt], wbase + (nt*16*PAD + kk*8) * 4);
                a[nt][0] = bits2tf32(a[nt][0]);
                a[nt][1] = bits2tf32(a[nt][1]);
                a[nt][2] = bits2tf32(a[nt][2]);
                a[nt][3] = bits2tf32(a[nt][3]);
            }
            uint32_t bb[4][2];
            #pragma unroll
            for (int bt = 0; bt < 4; bt++) {
                bb[bt][0] = f2tf32(sm[xbase + bt*8*PAD + kk*8]);
                bb[bt][1] = f2tf32(sm[xbase + bt*8*PAD + kk*8 + 4]);
            }
            #pragma unroll
            for (int nt = 0; nt < 4; nt++)
                #pragma unroll
                for (int bt = 0; bt < 4; bt++)
                    mma_tf32(acc[nt][bt], a[nt], bb[bt][0], bb[bt][1]);
        }
        __syncthreads();     // all reads of buf done before any refill of it
        const int nx = t + 3;
        if (nx < cnt) {
            const int s = nx & (STAGES - 1);
            if (tid == 0) MBAR_EXPECT_TX(sb + s*8, TXB);
            bulk128(bdst0 + s*SM_STAGE, bsrc + (size_t)(c0 + nx)*KC, sb + s*8);
        }
    }

    // epilogue: D rows = n, cols = b -> [n][b]-major partial stores
    float* outp = g_part[ksp];
    const int nrow = n0 + n0w + (lane >> 2);
    const int bcol = b0w + 2*(lane & 3);
    #pragma unroll
    for (int nt = 0; nt < 4; nt++) {
        #pragma unroll
        for (int bt = 0; bt < 4; bt++) {
            int n = nrow + nt*16;
            int b = bcol + bt*8;
            *(float2*)&outp[(size_t)n*B + b]     = make_float2(acc[nt][bt][0], acc[nt][bt][1]);
            *(float2*)&outp[(size_t)(n+8)*B + b] = make_float2(acc[nt][bt][2], acc[nt][bt][3]);
        }
    }
}

// ---------------- 5) activation + state writes ----------------------------
__device__ __forceinline__ float sigmoidf_(float v) { return 1.0f / (1.0f + expf(-v)); }

__global__ void act_kernel(int l, int sel,
                           const float* __restrict__ b_ih,
                           const float* __restrict__ b_hh,
                           float* __restrict__ out) {
    int idx = blockIdx.x * blockDim.x + threadIdx.x;   // 0..131071
    int b = idx & (B - 1);          // fast -> coalesced partial reads
    int u = idx >> 7;
    float gi = 0.f, gg = 0.f, go = 0.f;
    #pragma unroll
    for (int ks = 0; ks < KSPL; ks++) {
        const float* p = g_part[ks];
        gi += p[u*B + b];
        gg += p[(H + u)*B + b];
        go += p[(2*H + u)*B + b];
    }
    const float* bi = b_ih + l*4*H;
    const float* bh = b_hh + l*4*H;
    gi += bi[u]       + bh[u];
    gg += bi[2*H + u] + bh[2*H + u];
    go += bi[3*H + u] + bh[3*H + u];
    float c = sigmoidf_(gi) * tanhf(gg);
    float h = sigmoidf_(go) * tanhf(c);
    g_xt[sel ^ 1][b*H + u] = h;
    float m = (b < g_bslast) ? 1.0f : 0.0f;
    out[OUT_SH + (l*B + b)*H + u] = h * m;
    out[OUT_SC + (l*B + b)*H + u] = c * m;
}

// ---------------- 6) broadcast output [T, B, H] ----------------------------
__global__ void out_kernel(int sel, float* __restrict__ out) {
    int tg = blockIdx.x;     // 0..63 (groups of 8 t)
    int b  = blockIdx.y;     // 0..127
    int q  = threadIdx.x;    // 256 threads, float4 each
    int len = g_len[b];
    const float4 h = *(const float4*)&g_xt[sel][g_rank[b]*H + q*4];
    const float4 z = make_float4(0.f, 0.f, 0.f, 0.f);
    #pragma unroll
    for (int i = 0; i < 8; i++) {
        int t = tg*8 + i;
        float4 v = (t < len) ? h : z;
        __stcs((float4*)&out[(size_t)(t*B + b)*H + q*4], v);
    }
}

// ---------------- launcher -------------------------------------------------
extern "C" void kernel_launch(void* const* d_in, const int* in_sizes, int n_in,
                              void* d_out, int out_size) {
    const int*   x    = (const int*)d_in[0];
    const float* emb  = (const float*)d_in[1];
    const float* W_ih = (const float*)d_in[2];
    // d_in[3] = W_hh: multiplied by h0 == 0, never read
    const float* b_ih = (const float*)d_in[4];
    const float* b_hh = (const float*)d_in[5];
    float* out = (float*)d_out;

    cudaFuncSetAttribute(gemm_mma, cudaFuncAttributeMaxDynamicSharedMemorySize, SM_TOTAL);

    len_kernel<<<B, 32>>>(x);
    sort_kernel<<<1, B>>>(x);
    embed_kernel<<<B, 256>>>(emb);

    int sel = 0;
    for (int l = 0; l < NL; l++) {
        dim3 grid(NT, KSPL);
        gemm_mma<<<grid, 256, SM_TOTAL>>>(sel, W_ih + (size_t)l * 4 * H * H);
        act_kernel<<<(B * H) / 256, 256>>>(l, sel, b_ih, b_hh, out);
        sel ^= 1;
    }
    out_kernel<<<dim3(S/8, B), 256>>>(sel, out);
}

// round 9
// speedup vs baseline: 1.0772x; 1.0772x over previous
#include <cuda_runtime.h>
#include <cstdint>
#include <cstddef>

#define B 128
#define S 512
#define H 1024
#define NL 4
#define NCOL 3072      // only i,g,o gate blocks (f dead: c0=0; W_hh dead: h0=0)
#define KSPL 6         // K splits
#define NT 48          // N tiles of 64 -> 48 x 6 = 288 CTAs = one wave @ occ 2
#define BN 64
#define KC 32          // k-floats per chunk
#define PAD 36         // row pitch in floats (conflict-free LDS & ldmatrix)
#define STAGES 3

#define OUT_SH (S*B*H)            // 67108864
#define OUT_SC (S*B*H + NL*B*H)   // 67633152

// smem float offsets per stage: X (128 rows) then W (64 rows), PAD pitch
#define STG   (192*PAD)
#define XO(s) ((s)*STG)
#define WO(s) ((s)*STG + 128*PAD)
#define SM_FLOATS (STAGES*STG)                 // 20736 floats = 82944 B

// ---------------- scratch (device globals; no allocation allowed) ----------
__device__ __align__(16) float g_xt[2][B*H];           // tf32-rounded activations
__device__ __align__(16) float g_h[B*H];               // unrounded top-layer h
__device__ __align__(16) float g_part[KSPL][NCOL*B];   // [n][b]-major partials
__device__ int g_len[B];
__device__ int g_rank[B];
__device__ int g_sorted[B];
__device__ int g_tok0[B];
__device__ int g_bslast;

// ---------------- PTX helpers ----------------------------------------------
__device__ __forceinline__ uint32_t smem_u32(const void* p) {
    uint32_t a;
    asm("{ .reg .u64 t; cvta.to.shared.u64 t, %1; cvt.u32.u64 %0, t; }" : "=r"(a) : "l"(p));
    return a;
}
__device__ __forceinline__ uint32_t f2tf32(float x) {
    uint32_t u;
    asm("cvt.rna.tf32.f32 %0, %1;" : "=r"(u) : "f"(x));
    return u;
}
__device__ __forceinline__ float f2tf32f(float x) {
    return __uint_as_float(f2tf32(x));
}
__device__ __forceinline__ uint32_t bits2tf32(uint32_t r) {
    uint32_t u;
    asm("cvt.rna.tf32.f32 %0, %1;" : "=r"(u) : "f"(__uint_as_float(r)));
    return u;
}
__device__ __forceinline__ void cp16(uint32_t dst, const void* src) {
    asm volatile("cp.async.cg.shared.global [%0], [%1], 16;" :: "r"(dst), "l"(src));
}
#define CP_COMMIT() asm volatile("cp.async.commit_group;" ::: "memory")
#define CP_WAIT1()  asm volatile("cp.async.wait_group 1;" ::: "memory")

__device__ __forceinline__ void ldsm_x4(uint32_t* r, uint32_t addr) {
    asm volatile("ldmatrix.sync.aligned.m8n8.x4.shared.b16 {%0,%1,%2,%3}, [%4];"
                 : "=r"(r[0]), "=r"(r[1]), "=r"(r[2]), "=r"(r[3]) : "r"(addr));
}
__device__ __forceinline__ void mma_tf32(float* d, const uint32_t* a,
                                         uint32_t b0, uint32_t b1) {
    asm volatile(
        "mma.sync.aligned.m16n8k8.row.col.f32.tf32.tf32.f32 "
        "{%0,%1,%2,%3}, {%4,%5,%6,%7}, {%8,%9}, {%0,%1,%2,%3};"
        : "+f"(d[0]), "+f"(d[1]), "+f"(d[2]), "+f"(d[3])
        : "r"(a[0]), "r"(a[1]), "r"(a[2]), "r"(a[3]), "r"(b0), "r"(b1));
}

// ---------------- 1) lengths ----------------------------------------------
__global__ void len_kernel(const int* __restrict__ x) {
    int b = blockIdx.x, lane = threadIdx.x;
    int cnt = 0;
    #pragma unroll
    for (int s = lane; s < S; s += 32) cnt += (x[b*S + s] > 0);
    #pragma unroll
    for (int o = 16; o; o >>= 1) cnt += __shfl_down_sync(0xffffffffu, cnt, o);
    if (lane == 0) g_len[b] = cnt;
}

// ---------------- 2) stable descending argsort of 128 lengths -------------
__global__ void sort_kernel(const int* __restrict__ x) {
    __shared__ int slen[B];
    __shared__ int ssort[B];
    int b = threadIdx.x;
    slen[b] = g_len[b];
    __syncthreads();
    int lb = slen[b];
    int rank = 0, bs = 0;
    #pragma unroll 8
    for (int i = 0; i < B; i++) {
        int li = slen[i];
        rank += (li > lb) || (li == lb && i < b);
        bs += (li >= S);
    }
    g_rank[b] = rank;
    ssort[rank] = b;
    if (b == 0) g_bslast = bs;
    __syncthreads();
    int src = ssort[b];
    g_sorted[b] = src;
    g_tok0[b] = x[src * S];
}

// ---------------- 3) embedding gather (sorted order, tf32-rounded) --------
__global__ void embed_kernel(const float* __restrict__ emb) {
    int i = blockIdx.x;
    int t = threadIdx.x;       // 256 threads, 1 float4 each (H = 1024)
    int tok = g_tok0[i];
    float4 v = *(const float4*)&emb[tok*H + t*4];
    v.x = f2tf32f(v.x); v.y = f2tf32f(v.y);
    v.z = f2tf32f(v.z); v.w = f2tf32f(v.w);
    *(float4*)&g_xt[0][i*H + t*4] = v;
}

// ---------------- 4) tf32 mma.sync GEMM, BN=64, occ 2 ---------------------
// part[ks][n][b] = sum_{k in split} xt[b][k] * W[j(n)][k]
// mma-"A" = W (row-major n x k via ldmatrix b16 trick), mma-"B" = xt ([b][k])
__global__ __launch_bounds__(256, 2)
void gemm_mma(int sel, const float* __restrict__ W) {
    extern __shared__ __align__(16) float sm[];
    const uint32_t sb = smem_u32(sm);
    const int tid  = threadIdx.x;
    const int lane = tid & 31;
    const int warp = tid >> 5;            // 0..7
    const int wn = warp & 1;              // n half: 32 rows
    const int wb = warp >> 1;             // b quarter: 32 cols
    const int nt_ = blockIdx.x;           // 0..47
    const int ksp = blockIdx.y;           // 0..5
    const int n0 = nt_ * BN;
    const int j0 = (n0 < H) ? n0 : n0 + H;        // skip dead f-gate rows
    const int cnt = (ksp < 2) ? 6 : 5;            // chunks ({6,6,5,5,5,5} of 32)
    const int c0  = (ksp < 2) ? ksp*6 : 12 + (ksp-2)*5;
    const float* __restrict__ xt = g_xt[sel];

    // staging: X rows xr+i*32 (i<4), W rows xr+i*32 (i<2), 16B at kq
    const int xr = tid >> 3;
    const int kq = (tid & 7) * 4;

    // ldmatrix lane address pieces (W operand)
    const int row_in = (lane & 7) + ((lane >> 3) & 1) * 8;
    const int kadd   = (lane >> 4) * 4;
    const int n0w    = wn * 32;
    const int b0w    = wb * 32;

    float acc[2][4][4];
    #pragma unroll
    for (int nt = 0; nt < 2; nt++)
        #pragma unroll
        for (int bt = 0; bt < 4; bt++)
            #pragma unroll
            for (int q = 0; q < 4; q++) acc[nt][bt][q] = 0.f;

#define ISSUE_STAGE(s, c) do {                                                  \
    const int k0_ = (c0 + (c)) * KC;                                            \
    _Pragma("unroll")                                                           \
    for (int i = 0; i < 4; i++)                                                 \
        cp16(sb + (XO(s) + (xr + i*32)*PAD + kq)*4,                             \
             &xt[(size_t)(xr + i*32)*H + k0_ + kq]);                            \
    _Pragma("unroll")                                                           \
    for (int i = 0; i < 2; i++)                                                 \
        cp16(sb + (WO(s) + (xr + i*32)*PAD + kq)*4,                             \
             &W[(size_t)(j0 + xr + i*32)*H + k0_ + kq]);                        \
    CP_COMMIT();                                                                \
} while (0)

    // prologue: 2 stages in flight
    ISSUE_STAGE(0, 0);
    ISSUE_STAGE(1, 1);

    for (int t = 0; t < cnt; t++) {
        const int buf = t % STAGES;
        CP_WAIT1();
        __syncthreads();
        // refill the buffer computed at t-1 (synced above); buf t and t+1 live
        const int nx = t + 2;
        if (nx < cnt) ISSUE_STAGE(nx % STAGES, nx);
        else          CP_COMMIT();    // empty group keeps wait_group(1) aligned

        const uint32_t wbase = sb + (WO(buf) + (n0w + row_in)*PAD + kadd) * 4;
        const int      xbase = XO(buf) + (b0w + (lane >> 2))*PAD + (lane & 3);
        #pragma unroll
        for (int kk = 0; kk < 4; kk++) {          // 4 k-steps of 8
            uint32_t a[2][4];
            #pragma unroll
            for (int nt = 0; nt < 2; nt++) {
                ldsm_x4(a[nt], wbase + (nt*16*PAD + kk*8) * 4);
                a[nt][0] = bits2tf32(a[nt][0]);
                a[nt][1] = bits2tf32(a[nt][1]);
                a[nt][2] = bits2tf32(a[nt][2]);
                a[nt][3] = bits2tf32(a[nt][3]);
            }
            uint32_t bb[4][2];
            #pragma unroll
            for (int bt = 0; bt < 4; bt++) {       // xt pre-rounded: no cvt
                bb[bt][0] = __float_as_uint(sm[xbase + bt*8*PAD + kk*8]);
                bb[bt][1] = __float_as_uint(sm[xbase + bt*8*PAD + kk*8 + 4]);
            }
            #pragma unroll
            for (int nt = 0; nt < 2; nt++)
                #pragma unroll
                for (int bt = 0; bt < 4; bt++)
                    mma_tf32(acc[nt][bt], a[nt], bb[bt][0], bb[bt][1]);
        }
        __syncthreads();     // all reads of buf done before its refill next iter
    }
#undef ISSUE_STAGE

    // epilogue: D rows = n, cols = b -> [n][b]-major partial stores
    float* outp = g_part[ksp];
    const int nrow = n0 + n0w + (lane >> 2);
    const int bcol = b0w + 2*(lane & 3);
    #pragma unroll
    for (int nt = 0; nt < 2; nt++) {
        #pragma unroll
        for (int bt = 0; bt < 4; bt++) {
            int n = nrow + nt*16;
            int b = bcol + bt*8;
            *(float2*)&outp[(size_t)n*B + b]     = make_float2(acc[nt][bt][0], acc[nt][bt][1]);
            *(float2*)&outp[(size_t)(n+8)*B + b] = make_float2(acc[nt][bt][2], acc[nt][bt][3]);
        }
    }
}

// ---------------- 5) activation + state writes ----------------------------
__device__ __forceinline__ float sigmoidf_(float v) { return 1.0f / (1.0f + expf(-v)); }

__global__ void act_kernel(int l, int sel,
                           const float* __restrict__ b_ih,
                           const float* __restrict__ b_hh,
                           float* __restrict__ out) {
    int idx = blockIdx.x * blockDim.x + threadIdx.x;   // 0..131071
    int b = idx & (B - 1);          // fast -> coalesced partial reads
    int u = idx >> 7;
    float gi = 0.f, gg = 0.f, go = 0.f;
    #pragma unroll
    for (int ks = 0; ks < KSPL; ks++) {
        const float* p = g_part[ks];
        gi += p[u*B + b];
        gg += p[(H + u)*B + b];
        go += p[(2*H + u)*B + b];
    }
    const float* bi = b_ih + l*4*H;
    const float* bh = b_hh + l*4*H;
    gi += bi[u]       + bh[u];
    gg += bi[2*H + u] + bh[2*H + u];
    go += bi[3*H + u] + bh[3*H + u];
    float c = sigmoidf_(gi) * tanhf(gg);
    float h = sigmoidf_(go) * tanhf(c);
    g_xt[sel ^ 1][b*H + u] = f2tf32f(h);   // rounded feed for next GEMM
    g_h[b*H + u] = h;                      // exact h for output broadcast
    float m = (b < g_bslast) ? 1.0f : 0.0f;
    out[OUT_SH + (l*B + b)*H + u] = h * m;
    out[OUT_SC + (l*B + b)*H + u] = c * m;
}

// ---------------- 6) broadcast output [T, B, H] ----------------------------
__global__ void out_kernel(float* __restrict__ out) {
    int tg = blockIdx.x;     // 0..63 (groups of 8 t)
    int b  = blockIdx.y;     // 0..127
    int q  = threadIdx.x;    // 256 threads, float4 each
    int len = g_len[b];
    const float4 h = *(const float4*)&g_h[g_rank[b]*H + q*4];
    const float4 z = make_float4(0.f, 0.f, 0.f, 0.f);
    #pragma unroll
    for (int i = 0; i < 8; i++) {
        int t = tg*8 + i;
        float4 v = (t < len) ? h : z;
        __stcs((float4*)&out[(size_t)(t*B + b)*H + q*4], v);
    }
}

// ---------------- launcher -------------------------------------------------
extern "C" void kernel_launch(void* const* d_in, const int* in_sizes, int n_in,
                              void* d_out, int out_size) {
    const int*   x    = (const int*)d_in[0];
    const float* emb  = (const float*)d_in[1];
    const float* W_ih = (const float*)d_in[2];
    // d_in[3] = W_hh: multiplied by h0 == 0, never read
    const float* b_ih = (const float*)d_in[4];
    const float* b_hh = (const float*)d_in[5];
    float* out = (float*)d_out;

    cudaFuncSetAttribute(gemm_mma, cudaFuncAttributeMaxDynamicSharedMemorySize,
                         SM_FLOATS * (int)sizeof(float));

    len_kernel<<<B, 32>>>(x);
    sort_kernel<<<1, B>>>(x);
    embed_kernel<<<B, 256>>>(emb);

    int sel = 0;
    for (int l = 0; l < NL; l++) {
        dim3 grid(NT, KSPL);
        gemm_mma<<<grid, 256, SM_FLOATS * sizeof(float)>>>(sel, W_ih + (size_t)l * 4 * H * H);
        act_kernel<<<(B * H) / 256, 256>>>(l, sel, b_ih, b_hh, out);
        sel ^= 1;
    }
    out_kernel<<<dim3(S/8, B), 256>>>(out);
}